// round 3
// baseline (speedup 1.0000x reference)
#include <cuda_runtime.h>
#include <cuda_bf16.h>
#include <cstdint>

// LGConv scatter-sum: out[i] = sum over edges (src->i) of x[src].
// x: [N=100000, D=64] fp32; edge_index: [2, E=1250000] int64 OR int32
// (dtype detected on-device); out: [N, 64] fp32.
//
//  - detect_kernel: 1 thread decides whether edge_index is int64 or int32
//    (indices < 2^31, so int64 data has all-zero high words). Deterministic.
//  - scatter: 16 threads/edge, one float4 gather + one red.global.add.v4.f32
//    per thread. RED has no return value -> no long-scoreboard stall, and
//    v4 means 4x fewer atomic instructions than scalar atomicAdd.
//  - x (25.6 MB) and out (25.6 MB) both fit in the ~126 MB L2 -> after first
//    touch the gather + scatter traffic is L2-resident.

static constexpr int D = 64;
static constexpr int VEC = 4;
static constexpr int TPE = D / VEC;   // 16 threads per edge

__device__ int g_idx_is_i64;

__global__ void detect_idx_dtype_kernel(const void* __restrict__ ei)
{
    // If the buffer really holds int64 little-endian values < 2^31, every
    // high 32-bit word is zero. If it holds int32 indices, these words are
    // random node ids in [0,100000) -> all-zero chance ~1e-80.
    const int* as32 = (const int*)ei;
    int is64 = 1;
    #pragma unroll
    for (int i = 0; i < 16; i++) {
        if (as32[2 * i + 1] != 0) { is64 = 0; break; }
    }
    g_idx_is_i64 = is64;
}

__global__ __launch_bounds__(256)
void lgconv_scatter_kernel(const float* __restrict__ x,
                           const void* __restrict__ edge_index,
                           float* __restrict__ out,
                           int n_edges, int n_nodes)
{
    int idx = blockIdx.x * blockDim.x + threadIdx.x;
    int e = idx >> 4;          // edge id
    int k = idx & (TPE - 1);   // float4 chunk within the 64-float row
    if (e >= n_edges) return;

    int src, dst;
    if (g_idx_is_i64) {
        const long long* e64 = (const long long*)edge_index;
        src = (int)e64[e];
        dst = (int)e64[n_edges + e];
    } else {
        const int* e32 = (const int*)edge_index;
        src = e32[e];
        dst = e32[n_edges + e];
    }

    // Safety net: never fault on a bad index.
    if ((unsigned)src >= (unsigned)n_nodes || (unsigned)dst >= (unsigned)n_nodes)
        return;

    const float4 v = *reinterpret_cast<const float4*>(x + (size_t)src * D + (k << 2));

    float* dptr = out + (size_t)dst * D + (k << 2);
    asm volatile("red.global.add.v4.f32 [%0], {%1, %2, %3, %4};"
                 :: "l"(dptr), "f"(v.x), "f"(v.y), "f"(v.z), "f"(v.w)
                 : "memory");
}

extern "C" void kernel_launch(void* const* d_in, const int* in_sizes, int n_in,
                              void* d_out, int out_size)
{
    // Identify inputs by element count (robust to position of the scalar t):
    //   x:          6,400,000 elements (== out_size)
    //   edge_index: 2,500,000 elements (2*E, regardless of int32/int64 dtype)
    const float* x = nullptr;
    const void* edge_index = nullptr;
    long long e2 = 0;
    for (int i = 0; i < n_in; i++) {
        if (in_sizes[i] == out_size) {
            x = (const float*)d_in[i];
        } else if (in_sizes[i] > 1) {
            edge_index = d_in[i];
            e2 = in_sizes[i];
        }
    }
    int n_edges = (int)(e2 / 2);
    int n_nodes = out_size / D;
    float* out = (float*)d_out;

    // Output is poisoned to 0xAA and the graph replays -> zero it every launch.
    cudaMemsetAsync(out, 0, (size_t)out_size * sizeof(float), 0);

    detect_idx_dtype_kernel<<<1, 1>>>(edge_index);

    long long total_threads = (long long)n_edges * TPE;
    int block = 256;
    int grid = (int)((total_threads + block - 1) / block);
    lgconv_scatter_kernel<<<grid, block>>>(x, edge_index, out, n_edges, n_nodes);
}

// round 4
// speedup vs baseline: 1.1541x; 1.1541x over previous
#include <cuda_runtime.h>
#include <cuda_bf16.h>
#include <cstdint>

// LGConv scatter-sum: out[i] = sum over edges (src->i) of x[src].
// x: [N=100000, D=64] fp32; edge_index: [2, E=1250000] int64 or int32
// (detected on device); out: [N, 64] fp32.
//
// R4: CSR-on-the-fly. Instead of 20M RED.128 output atomics (the R3 binder:
// ~1.3 cyc/lane atomic issue cost ~= the whole 80us kernel), build a
// dst-bucketed permutation of edges each launch (hist + scan + fill,
// ~2.5M cheap 4B atomics), then do a pure gather-sum: one warp per node,
// register accumulation, one coalesced non-atomic 256B store per node.
// Also kills the d_out memset (full overwrite).

static constexpr int D = 64;
static constexpr int MAX_N = 100000;
static constexpr int MAX_E = 1250000;
static constexpr int SCAN_CHUNK = 1024;                       // elems per block in scan
static constexpr int MAX_SBLK = (MAX_N + SCAN_CHUNK - 1) / SCAN_CHUNK;  // 98

__device__ int g_idx_is_i64;
__device__ int g_deg[MAX_N];
__device__ int g_cursor[MAX_N];
__device__ int g_off[MAX_N + 1];
__device__ int g_blocksum[MAX_SBLK];
__device__ int g_perm[MAX_E];

__global__ void detect_idx_dtype_kernel(const void* __restrict__ ei)
{
    // int64 indices < 2^31 -> every high 32-bit word is zero.
    const int* as32 = (const int*)ei;
    int is64 = 1;
    #pragma unroll
    for (int i = 0; i < 16; i++)
        if (as32[2 * i + 1] != 0) { is64 = 0; break; }
    g_idx_is_i64 = is64;
}

__device__ __forceinline__ int load_idx(const void* ei, long long pos)
{
    if (g_idx_is_i64) return (int)((const long long*)ei)[pos];
    return ((const int*)ei)[pos];
}

// ---- Phase 1: histogram of dst --------------------------------------------
__global__ __launch_bounds__(256)
void hist_kernel(const void* __restrict__ ei, int n_edges, int n_nodes)
{
    int e = blockIdx.x * blockDim.x + threadIdx.x;
    if (e >= n_edges) return;
    int dst = load_idx(ei, (long long)n_edges + e);
    if ((unsigned)dst < (unsigned)n_nodes)
        atomicAdd(&g_deg[dst], 1);   // no return use -> REDG
}

// ---- Phase 2a: per-chunk partial sums -------------------------------------
__global__ __launch_bounds__(256)
void scan_partial_kernel(int n_nodes)
{
    __shared__ int sdata[256];
    int base = blockIdx.x * SCAN_CHUNK;
    int sum = 0;
    for (int i = threadIdx.x; i < SCAN_CHUNK; i += 256) {
        int idx = base + i;
        sum += (idx < n_nodes) ? g_deg[idx] : 0;
    }
    sdata[threadIdx.x] = sum;
    __syncthreads();
    for (int s = 128; s > 0; s >>= 1) {
        if (threadIdx.x < s) sdata[threadIdx.x] += sdata[threadIdx.x + s];
        __syncthreads();
    }
    if (threadIdx.x == 0) g_blocksum[blockIdx.x] = sdata[0];
}

// ---- Phase 2b: exclusive scan of chunk sums (single block) ----------------
__global__ void scan_blocksums_kernel(int nblocks)
{
    __shared__ int s[128];
    int t = threadIdx.x;
    int v = (t < nblocks) ? g_blocksum[t] : 0;
    s[t] = v;
    __syncthreads();
    for (int off = 1; off < 128; off <<= 1) {
        int u = (t >= off) ? s[t - off] : 0;
        __syncthreads();
        s[t] += u;
        __syncthreads();
    }
    if (t < nblocks) g_blocksum[t] = s[t] - v;   // exclusive
}

// ---- Phase 2c: final per-chunk exclusive scan -> off[], cursor[] ----------
__global__ __launch_bounds__(256)
void scan_final_kernel(int n_nodes, int n_edges)
{
    __shared__ int s[256];
    int base = blockIdx.x * SCAN_CHUNK;
    int bpfx = g_blocksum[blockIdx.x];

    // 4 consecutive elements per thread
    int v[4];
    int tsum = 0;
    #pragma unroll
    for (int j = 0; j < 4; j++) {
        int idx = base + threadIdx.x * 4 + j;
        v[j] = (idx < n_nodes) ? g_deg[idx] : 0;
        tsum += v[j];
    }
    s[threadIdx.x] = tsum;
    __syncthreads();
    for (int off = 1; off < 256; off <<= 1) {
        int u = (threadIdx.x >= (unsigned)off) ? s[threadIdx.x - off] : 0;
        __syncthreads();
        s[threadIdx.x] += u;
        __syncthreads();
    }
    int run = bpfx + s[threadIdx.x] - tsum;     // exclusive prefix for this thread
    #pragma unroll
    for (int j = 0; j < 4; j++) {
        int idx = base + threadIdx.x * 4 + j;
        if (idx < n_nodes) {
            g_off[idx] = run;
            g_cursor[idx] = run;
        }
        run += v[j];
    }
    if (blockIdx.x == 0 && threadIdx.x == 0)
        g_off[n_nodes] = n_edges;
}

// ---- Phase 3: bucket-fill the edge permutation ----------------------------
__global__ __launch_bounds__(256)
void fill_perm_kernel(const void* __restrict__ ei, int n_edges, int n_nodes)
{
    int e = blockIdx.x * blockDim.x + threadIdx.x;
    if (e >= n_edges) return;
    int src = load_idx(ei, e);
    int dst = load_idx(ei, (long long)n_edges + e);
    if ((unsigned)src >= (unsigned)n_nodes || (unsigned)dst >= (unsigned)n_nodes)
        return;
    int pos = atomicAdd(&g_cursor[dst], 1);
    g_perm[pos] = src;
}

// ---- Phase 4: gather-sum, one warp per node -------------------------------
__global__ __launch_bounds__(256)
void gather_sum_kernel(const float* __restrict__ x,
                       float* __restrict__ out, int n_nodes)
{
    int warp = (blockIdx.x * blockDim.x + threadIdx.x) >> 5;
    int lane = threadIdx.x & 31;
    if (warp >= n_nodes) return;

    int n = warp;
    int s = g_off[n];
    int e = g_off[n + 1];

    int slot = lane >> 4;        // which of 2 edges in flight
    int c = lane & 15;           // float4 chunk within the 64-float row

    float4 acc = make_float4(0.f, 0.f, 0.f, 0.f);
    for (int j = s + slot; j < e; j += 2) {
        int src = g_perm[j];
        const float4 v = *reinterpret_cast<const float4*>(
            x + (size_t)src * D + (c << 2));
        acc.x += v.x; acc.y += v.y; acc.z += v.z; acc.w += v.w;
    }

    // fold slot 1 into slot 0
    acc.x += __shfl_down_sync(0xffffffffu, acc.x, 16);
    acc.y += __shfl_down_sync(0xffffffffu, acc.y, 16);
    acc.z += __shfl_down_sync(0xffffffffu, acc.z, 16);
    acc.w += __shfl_down_sync(0xffffffffu, acc.w, 16);

    if (slot == 0)
        *reinterpret_cast<float4*>(out + (size_t)n * D + (c << 2)) = acc;
}

extern "C" void kernel_launch(void* const* d_in, const int* in_sizes, int n_in,
                              void* d_out, int out_size)
{
    const float* x = nullptr;
    const void* edge_index = nullptr;
    long long e2 = 0;
    for (int i = 0; i < n_in; i++) {
        if (in_sizes[i] == out_size) {
            x = (const float*)d_in[i];
        } else if (in_sizes[i] > 1) {
            edge_index = d_in[i];
            e2 = in_sizes[i];
        }
    }
    int n_edges = (int)(e2 / 2);
    int n_nodes = out_size / D;
    if (n_edges > MAX_E) n_edges = MAX_E;    // scratch capacity guard
    if (n_nodes > MAX_N) n_nodes = MAX_N;
    float* out = (float*)d_out;

    void* deg_addr = nullptr;
    cudaGetSymbolAddress(&deg_addr, g_deg);

    detect_idx_dtype_kernel<<<1, 1>>>(edge_index);
    cudaMemsetAsync(deg_addr, 0, (size_t)n_nodes * sizeof(int), 0);

    int eblocks = (n_edges + 255) / 256;
    hist_kernel<<<eblocks, 256>>>(edge_index, n_edges, n_nodes);

    int sblocks = (n_nodes + SCAN_CHUNK - 1) / SCAN_CHUNK;
    scan_partial_kernel<<<sblocks, 256>>>(n_nodes);
    scan_blocksums_kernel<<<1, 128>>>(sblocks);
    scan_final_kernel<<<sblocks, 256>>>(n_nodes, n_edges);

    fill_perm_kernel<<<eblocks, 256>>>(edge_index, n_edges, n_nodes);

    int gblocks = (n_nodes * 32 + 255) / 256;
    gather_sum_kernel<<<gblocks, 256>>>(x, out, n_nodes);
}